// round 15
// baseline (speedup 1.0000x reference)
#include <cuda_runtime.h>
#include <cuda_fp16.h>
#include <cstdint>

// Problem constants (fixed by the reference)
#define NTOK   8192
#define DMODEL 1024
#define DHID   4096
#define NEXP   8
#define CAP    2048

// ---------------- scratch (allocation-free: __device__ globals) ------------
__device__ int   g_route[NTOK];
__device__ int   g_toklist[NEXP * CAP];
__device__ int   g_count[NEXP];

// single-plane fp16 operands
__device__ __align__(16) __half g_xH[(size_t)NTOK * DMODEL];
__device__ __align__(16) __half g_w1H[(size_t)NEXP * DMODEL * DHID];  // [e][k][n]
__device__ __align__(16) __half g_w2H[(size_t)NEXP * DHID * DMODEL];  // [e][k][n]
__device__ __align__(16) __half g_hH[(size_t)NEXP * CAP * DHID];      // [e][row][k]

// ---------------- PTX helpers ----------------------------------------------
__device__ __forceinline__ uint32_t smem_u32(const void* p) {
    return (uint32_t)__cvta_generic_to_shared(p);
}

__device__ __forceinline__ void mma_f16(float* c, const uint32_t* a, const uint32_t* b) {
    asm volatile(
        "mma.sync.aligned.m16n8k16.row.col.f32.f16.f16.f32 "
        "{%0,%1,%2,%3}, {%4,%5,%6,%7}, {%8,%9}, {%0,%1,%2,%3};"
        : "+f"(c[0]), "+f"(c[1]), "+f"(c[2]), "+f"(c[3])
        : "r"(a[0]), "r"(a[1]), "r"(a[2]), "r"(a[3]), "r"(b[0]), "r"(b[1]));
}

__device__ __forceinline__ void ldsm_x4(uint32_t& r0, uint32_t& r1,
                                        uint32_t& r2, uint32_t& r3, uint32_t addr) {
    asm volatile("ldmatrix.sync.aligned.m8n8.x4.shared.b16 {%0,%1,%2,%3}, [%4];"
        : "=r"(r0), "=r"(r1), "=r"(r2), "=r"(r3) : "r"(addr));
}

__device__ __forceinline__ void ldsm_x4_t(uint32_t& r0, uint32_t& r1,
                                          uint32_t& r2, uint32_t& r3, uint32_t addr) {
    asm volatile("ldmatrix.sync.aligned.m8n8.x4.trans.shared.b16 {%0,%1,%2,%3}, [%4];"
        : "=r"(r0), "=r"(r1), "=r"(r2), "=r"(r3) : "r"(addr));
}

// B sub-tile byte offset with XOR swizzle (k row = 256B; validated layout)
__device__ __forceinline__ uint32_t bswz(int k, int nbyte) {
    return (uint32_t)(k * 256 + (nbyte ^ ((k & 7) << 4)));
}

__device__ __forceinline__ void cp_async16(uint32_t dst, const void* src, int srcSize) {
    asm volatile("cp.async.cg.shared.global [%0], [%1], 16, %2;"
        :: "r"(dst), "l"(src), "r"(srcSize) : "memory");
}
#define CP_COMMIT() asm volatile("cp.async.commit_group;" ::: "memory")
#define CP_WAIT2()  asm volatile("cp.async.wait_group 2;" ::: "memory")

// ---------------- router: logits + argmax (top_k = 1) ---------------------
__global__ __launch_bounds__(256) void moe_router(const float* __restrict__ x,
                                                  const float* __restrict__ Wg,
                                                  const float* __restrict__ bg) {
    __shared__ float sWgT[NEXP][DMODEL];
    int tid = threadIdx.x;
    for (int i = tid; i < DMODEL * NEXP; i += 256) {
        int d = i >> 3, e = i & 7;
        sWgT[e][d] = Wg[i];
    }
    __syncthreads();

    int wid = tid >> 5, lane = tid & 31;
    int token = blockIdx.x * 8 + wid;
    const float* xr = x + (size_t)token * DMODEL;

    float acc[NEXP];
#pragma unroll
    for (int e = 0; e < NEXP; e++) acc[e] = 0.f;
    for (int d = lane; d < DMODEL; d += 32) {
        float xv = xr[d];
#pragma unroll
        for (int e = 0; e < NEXP; e++) acc[e] += xv * sWgT[e][d];
    }
#pragma unroll
    for (int e = 0; e < NEXP; e++) {
#pragma unroll
        for (int off = 16; off > 0; off >>= 1)
            acc[e] += __shfl_xor_sync(0xffffffffu, acc[e], off);
    }
    if (lane == 0) {
        int best = 0;
        float bv = acc[0] + bg[0];
#pragma unroll
        for (int e = 1; e < NEXP; e++) {
            float v = acc[e] + bg[e];
            if (v > bv) { bv = v; best = e; }   // first-max tie-break
        }
        g_route[token] = best;
    }
}

// ---------------- ordered capacity scan ------------------------------------
__global__ __launch_bounds__(256) void moe_scan() {
    int tid = threadIdx.x;
    for (int i = tid; i < NEXP * CAP; i += 256) g_toklist[i] = -1;
    __syncthreads();
    int wid = tid >> 5, lane = tid & 31;   // wid == expert id
    int base = 0;
    for (int c = 0; c < NTOK / 32; c++) {
        int token = c * 32 + lane;
        int r = g_route[token];
        unsigned mask = __ballot_sync(0xffffffffu, r == wid);
        if (r == wid) {
            int pos = base + __popc(mask & ((1u << lane) - 1u));
            if (pos < CAP) g_toklist[wid * CAP + pos] = token;
        }
        base += __popc(mask);
    }
    if (lane == 0) g_count[wid] = base < CAP ? base : CAP;
}

// ---------------- fp32 -> fp16 converts (dest chosen DEVICE-SIDE) -----------
// __device__ array symbols must never be passed as kernel args from host code
// (host shadow address + GB300 ATS silently writes host memory).
// 8 floats per thread (2 independent float4 chains) for higher MLP.
__global__ __launch_bounds__(256) void convert_f16(const float* __restrict__ src,
                                                   int which) {
    __half* d = (which == 0) ? g_xH : (which == 1) ? g_w1H : g_w2H;
    size_t i = ((size_t)blockIdx.x * 256 + threadIdx.x) * 8;
    float4 v0 = *(const float4*)(src + i);
    float4 v1 = *(const float4*)(src + i + 4);
    __half2 A0 = {__float2half_rn(v0.x), __float2half_rn(v0.y)};
    __half2 A1 = {__float2half_rn(v0.z), __float2half_rn(v0.w)};
    __half2 B0 = {__float2half_rn(v1.x), __float2half_rn(v1.y)};
    __half2 B1 = {__float2half_rn(v1.z), __float2half_rn(v1.w)};
    *(uint4*)(d + i) = make_uint4(*(uint32_t*)&A0, *(uint32_t*)&A1,
                                  *(uint32_t*)&B0, *(uint32_t*)&B1);
}

// ---------------- single-pass fp16 tensor-core GEMMs, 512 threads -----------
// Block tile 128x256, BK=64, cp.async 4-stage pipeline. 16 warps in a
// 4(M) x 4(N) grid; warp tile 32x64 via 2 m16 x 8 n8, fp16 in, fp32 acc.
// MODE 1 uses SPLITK=4: blockIdx.x = colTile + nColTiles*split; each split
// covers K/4 and combines partials via fp32 atomicAdd (out pre-zeroed);
// split 0 adds the bias. Fixes the 1.73->2 wave tail (~35us).

#define BM 128
#define BN 256
#define BK 64
#define A_STRIDE 72                    // fp16 units per A row (64 data + 8 pad)
#define A_PLANE  (BM * A_STRIDE * 2)   // 18432 B
#define SUBB     (BK * 256)            // 16384 B per 128-col sub-tile
#define B_PLANE  (2 * SUBB)            // 32768 B
#define STAGE_B  (A_PLANE + B_PLANE)   // 51200 B
#define NSTAGE   4
#define FFN_SMEM (NSTAGE * STAGE_B)    // 204800 B

template <int MODE, int SPLITK>
__global__ __launch_bounds__(512, 1) void moe_ffn(const float* __restrict__ bias_g,
                                                  float* __restrict__ outg) {
    const int Ktot = (MODE == 0) ? DMODEL : DHID;
    const int Ntot = (MODE == 0) ? DHID : DMODEL;
    const int nColTiles = Ntot / BN;
    const int kLen = Ktot / SPLITK;

    int e = blockIdx.z;
    int count = g_count[e];
    int rowBase = blockIdx.y * BM;
    if (rowBase >= count) return;
    int colTile = blockIdx.x % nColTiles;
    int split   = blockIdx.x / nColTiles;
    int colBase = colTile * BN;
    int kBase   = split * kLen;

    extern __shared__ __align__(16) char dyn[];
    __shared__ int sTok[BM];

    int tid = threadIdx.x;
    if (tid < BM) {
        int row = rowBase + tid;
        sTok[tid] = (row < count) ? g_toklist[e * CAP + row] : -1;
    }
    __syncthreads();

    const float* bias = bias_g + (size_t)e * Ntot + colBase;
    uint32_t smBase = smem_u32(dyn);

    int warpId = tid >> 5, lane = tid & 31;
    int warpM = warpId & 3;            // M offset *32
    int warpN = warpId >> 2;           // N offset *64
    int gid = lane >> 2, tig = lane & 3;

    int lm_m  = lane >> 3;             // matrix index 0..3
    int lm_rr = lane & 7;
    int lm_kd = (lm_m & 1) * 8 + lm_rr;   // B: k offset within k16
    int lm_nd = (lm_m >> 1) * 8;          // B: n offset within n16 panel
    int aLmRow = (lm_m & 1) * 8 + lm_rr;  // A: row within m16
    int aLmCol = (lm_m >> 1) * 8;         // A: k offset within k16

    float acc[2][8][4];
#pragma unroll
    for (int mi = 0; mi < 2; mi++)
#pragma unroll
        for (int ni = 0; ni < 8; ni++)
#pragma unroll
            for (int q = 0; q < 4; q++) acc[mi][ni][q] = 0.f;

    // ---- copy-thread indices (512 threads, 6 cp.async each per stage) ----
    int aRow  = tid >> 2;              // A row (0..127), 4 threads/row
    int aSeg  = (tid & 3) * 16;        // k offset 0,16,32,48 (fp16 units)
    int bRow  = tid >> 3;              // B k row (0..63), 8 threads/row
    int bCol  = (tid & 7) * 16;        // B n offset within 128-col sub-tile

    int tokA = (MODE == 0) ? sTok[aRow] : -1;
    bool aValid = (MODE == 0) ? (tokA >= 0) : ((rowBase + aRow) < count);
    int aSize = aValid ? 16 : 0;
    const __half* aP;
    if (MODE == 0) {
        aP = g_xH + (size_t)(tokA < 0 ? 0 : tokA) * DMODEL + kBase;
    } else {
        aP = g_hH + ((size_t)e * CAP + rowBase + aRow) * (size_t)DHID + kBase;
    }
    const __half* bP = ((MODE == 0) ? g_w1H : g_w2H)
        + (size_t)e * Ktot * Ntot + (size_t)(kBase + bRow) * Ntot + colBase + bCol;

    uint32_t aDst  = (uint32_t)aRow * (A_STRIDE * 2) + (uint32_t)aSeg * 2;  // bytes
    uint32_t bDst0 = bswz(bRow, bCol * 2);
    uint32_t bDst1 = bswz(bRow, bCol * 2 + 16);
    const int nIter = kLen / BK;

    auto issue_stage = [&](int i) {
        uint32_t base = smBase + (uint32_t)(i % NSTAGE) * STAGE_B;
        int k0 = i * BK;
        const __half* bSrc = bP + (size_t)k0 * Ntot;
        cp_async16(base + aDst,       aP + k0 + aSeg,     aSize);
        cp_async16(base + aDst + 16u, aP + k0 + aSeg + 8, aSize);
        uint32_t bb = base + A_PLANE;
#pragma unroll
        for (int sub = 0; sub < 2; sub++) {           // two 128-col sub-tiles
            cp_async16(bb + bDst0, bSrc,     16);
            cp_async16(bb + bDst1, bSrc + 8, 16);
            bb += SUBB;
            bSrc += 128;
        }
    };

    issue_stage(0); CP_COMMIT();
    issue_stage(1); CP_COMMIT();
    issue_stage(2); CP_COMMIT();

    for (int i = 0; i < nIter; i++) {
        CP_WAIT2();            // stage i landed (<= 2 newer groups pending)
        __syncthreads();
        if (i + 3 < nIter) issue_stage(i + 3);
        CP_COMMIT();

        uint32_t base = smBase + (uint32_t)(i % NSTAGE) * STAGE_B;
        uint32_t pA = base;
        uint32_t pB = base + A_PLANE;

#pragma unroll
        for (int s = 0; s < 4; s++) {
            int kk = s * 16;
            // ---- A fragments via ldmatrix.x4 (non-trans) ----
            uint32_t aF[2][4];
#pragma unroll
            for (int mi = 0; mi < 2; mi++) {
                uint32_t ao = pA + (uint32_t)(((warpM * 32 + mi * 16 + aLmRow) * A_STRIDE
                                               + kk + aLmCol) * 2);
                ldsm_x4(aF[mi][0], aF[mi][1], aF[mi][2], aF[mi][3], ao);
            }
            // ---- B fragments: warp covers 64 cols = 4 x n16 panels ----
            uint32_t bh[4][4];
#pragma unroll
            for (int u = 0; u < 4; u++) {
                int n0 = warpN * 64 + u * 16;
                uint32_t off = (uint32_t)((n0 >> 7) * SUBB)
                             + bswz(kk + lm_kd, ((n0 & 127) + lm_nd) * 2);
                ldsm_x4_t(bh[u][0], bh[u][1], bh[u][2], bh[u][3], pB + off);
            }
            // ---- MMAs (16 distinct accumulators; no consecutive RAW) ----
#pragma unroll
            for (int ni = 0; ni < 8; ni++) {
                uint32_t bp[2] = { bh[ni >> 1][(ni & 1) * 2], bh[ni >> 1][(ni & 1) * 2 + 1] };
#pragma unroll
                for (int mi = 0; mi < 2; mi++) mma_f16(acc[mi][ni], aF[mi], bp);
            }
        }
        __syncthreads();       // all reads of stage i done before it is rewritten
    }

    // ---- epilogue ----
    bool addBias = (split == 0);
#pragma unroll
    for (int mi = 0; mi < 2; mi++) {
#pragma unroll
        for (int rsel = 0; rsel < 2; rsel++) {
            int rloc = warpM * 32 + mi * 16 + gid + rsel * 8;
            int tok = sTok[rloc];
            if (tok < 0) continue;
#pragma unroll
            for (int ni = 0; ni < 8; ni++) {
                int cloc = warpN * 64 + ni * 8 + tig * 2;
                float2 bv = *(const float2*)(bias + cloc);
                float v0 = acc[mi][ni][rsel * 2 + 0];
                float v1 = acc[mi][ni][rsel * 2 + 1];
                if (addBias) { v0 += bv.x; v1 += bv.y; }
                if (MODE == 0) {
                    v0 = v0 > 0.f ? v0 : 0.f;
                    v1 = v1 > 0.f ? v1 : 0.f;
                    __half2 H = {__float2half_rn(v0), __float2half_rn(v1)};
                    size_t o = ((size_t)e * CAP + rowBase + rloc) * DHID + colBase + cloc;
                    *(uint32_t*)(g_hH + o) = *(uint32_t*)&H;
                } else {
                    float* op = outg + (size_t)tok * DMODEL + colBase + cloc;
                    if (SPLITK == 1) {
                        *(float2*)op = make_float2(v0, v1);
                    } else {
                        atomicAdd(op, v0);
                        atomicAdd(op + 1, v1);
                    }
                }
            }
        }
    }
}

// ---------------- launch ----------------------------------------------------
#define SPLITK2 4

extern "C" void kernel_launch(void* const* d_in, const int* in_sizes, int n_in,
                              void* d_out, int out_size) {
    const float* x  = (const float*)d_in[0];
    const float* Wg = (const float*)d_in[1];
    const float* bg = (const float*)d_in[2];
    const float* W1 = (const float*)d_in[3];
    const float* b1 = (const float*)d_in[4];
    const float* W2 = (const float*)d_in[5];
    const float* b2 = (const float*)d_in[6];
    float* out = (float*)d_out;

    cudaFuncSetAttribute((const void*)moe_ffn<0, 1>,
                         cudaFuncAttributeMaxDynamicSharedMemorySize, FFN_SMEM);
    cudaFuncSetAttribute((const void*)moe_ffn<1, SPLITK2>,
                         cudaFuncAttributeMaxDynamicSharedMemorySize, FFN_SMEM);

    cudaMemsetAsync(d_out, 0, (size_t)out_size * sizeof(float));

    moe_router<<<NTOK / 8, 256>>>(x, Wg, bg);
    moe_scan<<<1, 256>>>();
    convert_f16<<<(NTOK * DMODEL) / 2048, 256>>>(x, 0);
    convert_f16<<<(NEXP * DMODEL * DHID) / 2048, 256>>>(W1, 1);
    convert_f16<<<(NEXP * DHID * DMODEL) / 2048, 256>>>(W2, 2);

    moe_ffn<0, 1><<<dim3(DHID / BN, CAP / BM, NEXP), 512, FFN_SMEM>>>(b1, nullptr);
    moe_ffn<1, SPLITK2><<<dim3((DMODEL / BN) * SPLITK2, CAP / BM, NEXP), 512, FFN_SMEM>>>(b2, out);
}

// round 16
// speedup vs baseline: 1.0482x; 1.0482x over previous
#include <cuda_runtime.h>
#include <cuda_fp16.h>
#include <cstdint>

// Problem constants (fixed by the reference)
#define NTOK   8192
#define DMODEL 1024
#define DHID   4096
#define NEXP   8
#define CAP    2048

// ---------------- scratch (allocation-free: __device__ globals) ------------
__device__ int   g_route[NTOK];
__device__ int   g_toklist[NEXP * CAP];
__device__ int   g_count[NEXP];

// single-plane fp16 operands
__device__ __align__(16) __half g_xH[(size_t)NTOK * DMODEL];
__device__ __align__(16) __half g_w1H[(size_t)NEXP * DMODEL * DHID];  // [e][k][n]
__device__ __align__(16) __half g_w2H[(size_t)NEXP * DHID * DMODEL];  // [e][k][n]
__device__ __align__(16) __half g_hH[(size_t)NEXP * CAP * DHID];      // [e][row][k]

// ---------------- PTX helpers ----------------------------------------------
__device__ __forceinline__ uint32_t smem_u32(const void* p) {
    return (uint32_t)__cvta_generic_to_shared(p);
}

__device__ __forceinline__ void mma_f16(float* c, const uint32_t* a, const uint32_t* b) {
    asm volatile(
        "mma.sync.aligned.m16n8k16.row.col.f32.f16.f16.f32 "
        "{%0,%1,%2,%3}, {%4,%5,%6,%7}, {%8,%9}, {%0,%1,%2,%3};"
        : "+f"(c[0]), "+f"(c[1]), "+f"(c[2]), "+f"(c[3])
        : "r"(a[0]), "r"(a[1]), "r"(a[2]), "r"(a[3]), "r"(b[0]), "r"(b[1]));
}

__device__ __forceinline__ void ldsm_x4(uint32_t& r0, uint32_t& r1,
                                        uint32_t& r2, uint32_t& r3, uint32_t addr) {
    asm volatile("ldmatrix.sync.aligned.m8n8.x4.shared.b16 {%0,%1,%2,%3}, [%4];"
        : "=r"(r0), "=r"(r1), "=r"(r2), "=r"(r3) : "r"(addr));
}

__device__ __forceinline__ void ldsm_x4_t(uint32_t& r0, uint32_t& r1,
                                          uint32_t& r2, uint32_t& r3, uint32_t addr) {
    asm volatile("ldmatrix.sync.aligned.m8n8.x4.trans.shared.b16 {%0,%1,%2,%3}, [%4];"
        : "=r"(r0), "=r"(r1), "=r"(r2), "=r"(r3) : "r"(addr));
}

// B sub-tile byte offset with XOR swizzle (k row = 256B; validated layout)
__device__ __forceinline__ uint32_t bswz(int k, int nbyte) {
    return (uint32_t)(k * 256 + (nbyte ^ ((k & 7) << 4)));
}

__device__ __forceinline__ void cp_async16(uint32_t dst, const void* src, int srcSize) {
    asm volatile("cp.async.cg.shared.global [%0], [%1], 16, %2;"
        :: "r"(dst), "l"(src), "r"(srcSize) : "memory");
}
#define CP_COMMIT() asm volatile("cp.async.commit_group;" ::: "memory")
#define CP_WAIT2()  asm volatile("cp.async.wait_group 2;" ::: "memory")

// ---------------- router: logits + argmax (top_k = 1) ---------------------
__global__ __launch_bounds__(256) void moe_router(const float* __restrict__ x,
                                                  const float* __restrict__ Wg,
                                                  const float* __restrict__ bg) {
    __shared__ float sWgT[NEXP][DMODEL];
    int tid = threadIdx.x;
    for (int i = tid; i < DMODEL * NEXP; i += 256) {
        int d = i >> 3, e = i & 7;
        sWgT[e][d] = Wg[i];
    }
    __syncthreads();

    int wid = tid >> 5, lane = tid & 31;
    int token = blockIdx.x * 8 + wid;
    const float* xr = x + (size_t)token * DMODEL;

    float acc[NEXP];
#pragma unroll
    for (int e = 0; e < NEXP; e++) acc[e] = 0.f;
    for (int d = lane; d < DMODEL; d += 32) {
        float xv = xr[d];
#pragma unroll
        for (int e = 0; e < NEXP; e++) acc[e] += xv * sWgT[e][d];
    }
#pragma unroll
    for (int e = 0; e < NEXP; e++) {
#pragma unroll
        for (int off = 16; off > 0; off >>= 1)
            acc[e] += __shfl_xor_sync(0xffffffffu, acc[e], off);
    }
    if (lane == 0) {
        int best = 0;
        float bv = acc[0] + bg[0];
#pragma unroll
        for (int e = 1; e < NEXP; e++) {
            float v = acc[e] + bg[e];
            if (v > bv) { bv = v; best = e; }   // first-max tie-break
        }
        g_route[token] = best;
    }
}

// ---------------- ordered capacity scan ------------------------------------
__global__ __launch_bounds__(256) void moe_scan() {
    int tid = threadIdx.x;
    for (int i = tid; i < NEXP * CAP; i += 256) g_toklist[i] = -1;
    __syncthreads();
    int wid = tid >> 5, lane = tid & 31;   // wid == expert id
    int base = 0;
    for (int c = 0; c < NTOK / 32; c++) {
        int token = c * 32 + lane;
        int r = g_route[token];
        unsigned mask = __ballot_sync(0xffffffffu, r == wid);
        if (r == wid) {
            int pos = base + __popc(mask & ((1u << lane) - 1u));
            if (pos < CAP) g_toklist[wid * CAP + pos] = token;
        }
        base += __popc(mask);
    }
    if (lane == 0) g_count[wid] = base < CAP ? base : CAP;
}

// ---------------- fused fp32 -> fp16 convert (ONE launch, dest DEVICE-SIDE) -
// Block ranges: [0, XB) -> x, [XB, XB+WB) -> W1, [XB+WB, XB+2*WB) -> W2.
// 16 floats per thread (4 independent float4 chains) for high MLP.
// __device__ array symbols must never be passed as kernel args from host code
// (host shadow address + GB300 ATS silently writes host memory).
#define CVT_PER_BLK 4096                                  // floats per block
#define XB ((NTOK * DMODEL) / CVT_PER_BLK)                // 2048
#define WB ((NEXP * DMODEL * DHID) / CVT_PER_BLK)         // 8192
#define CVT_BLOCKS (XB + 2 * WB)                          // 18432

__global__ __launch_bounds__(256) void convert_all(const float* __restrict__ x,
                                                   const float* __restrict__ W1,
                                                   const float* __restrict__ W2) {
    int b = blockIdx.x;
    const float* src;
    __half* dst;
    if (b < XB)            { src = x;  dst = g_xH; }
    else if (b < XB + WB)  { src = W1; dst = g_w1H; b -= XB; }
    else                   { src = W2; dst = g_w2H; b -= XB + WB; }

    size_t i = ((size_t)b * 256 + threadIdx.x) * 16;
    float4 v0 = *(const float4*)(src + i);
    float4 v1 = *(const float4*)(src + i + 4);
    float4 v2 = *(const float4*)(src + i + 8);
    float4 v3 = *(const float4*)(src + i + 12);
    __half2 A0 = {__float2half_rn(v0.x), __float2half_rn(v0.y)};
    __half2 A1 = {__float2half_rn(v0.z), __float2half_rn(v0.w)};
    __half2 B0 = {__float2half_rn(v1.x), __float2half_rn(v1.y)};
    __half2 B1 = {__float2half_rn(v1.z), __float2half_rn(v1.w)};
    __half2 C0 = {__float2half_rn(v2.x), __float2half_rn(v2.y)};
    __half2 C1 = {__float2half_rn(v2.z), __float2half_rn(v2.w)};
    __half2 D0 = {__float2half_rn(v3.x), __float2half_rn(v3.y)};
    __half2 D1 = {__float2half_rn(v3.z), __float2half_rn(v3.w)};
    *(uint4*)(dst + i)     = make_uint4(*(uint32_t*)&A0, *(uint32_t*)&A1,
                                        *(uint32_t*)&B0, *(uint32_t*)&B1);
    *(uint4*)(dst + i + 8) = make_uint4(*(uint32_t*)&C0, *(uint32_t*)&C1,
                                        *(uint32_t*)&D0, *(uint32_t*)&D1);
}

// ---------------- single-pass fp16 tensor-core GEMMs, 512 threads -----------
// Block tile 128x256, BK=64, cp.async 4-stage pipeline. 16 warps in a
// 4(M) x 4(N) grid; warp tile 32x64 via 2 m16 x 8 n8, fp16 in, fp32 acc.
// (R14-validated configuration: 97% of the mma.sync issue roofline.)

#define BM 128
#define BN 256
#define BK 64
#define A_STRIDE 72                    // fp16 units per A row (64 data + 8 pad)
#define A_PLANE  (BM * A_STRIDE * 2)   // 18432 B
#define SUBB     (BK * 256)            // 16384 B per 128-col sub-tile
#define B_PLANE  (2 * SUBB)            // 32768 B
#define STAGE_B  (A_PLANE + B_PLANE)   // 51200 B
#define NSTAGE   4
#define FFN_SMEM (NSTAGE * STAGE_B)    // 204800 B

template <int MODE>
__global__ __launch_bounds__(512, 1) void moe_ffn(const float* __restrict__ bias_g,
                                                  float* __restrict__ outg) {
    const int Ktot = (MODE == 0) ? DMODEL : DHID;
    const int Ntot = (MODE == 0) ? DHID : DMODEL;

    int e = blockIdx.z;
    int count = g_count[e];
    int rowBase = blockIdx.y * BM;
    if (rowBase >= count) return;
    int colBase = blockIdx.x * BN;

    extern __shared__ __align__(16) char dyn[];
    __shared__ int sTok[BM];

    int tid = threadIdx.x;
    if (tid < BM) {
        int row = rowBase + tid;
        sTok[tid] = (row < count) ? g_toklist[e * CAP + row] : -1;
    }
    __syncthreads();

    const float* bias = bias_g + (size_t)e * Ntot + colBase;
    uint32_t smBase = smem_u32(dyn);

    int warpId = tid >> 5, lane = tid & 31;
    int warpM = warpId & 3;            // M offset *32
    int warpN = warpId >> 2;           // N offset *64
    int gid = lane >> 2, tig = lane & 3;

    int lm_m  = lane >> 3;             // matrix index 0..3
    int lm_rr = lane & 7;
    int lm_kd = (lm_m & 1) * 8 + lm_rr;   // B: k offset within k16
    int lm_nd = (lm_m >> 1) * 8;          // B: n offset within n16 panel
    int aLmRow = (lm_m & 1) * 8 + lm_rr;  // A: row within m16
    int aLmCol = (lm_m >> 1) * 8;         // A: k offset within k16

    float acc[2][8][4];
#pragma unroll
    for (int mi = 0; mi < 2; mi++)
#pragma unroll
        for (int ni = 0; ni < 8; ni++)
#pragma unroll
            for (int q = 0; q < 4; q++) acc[mi][ni][q] = 0.f;

    // ---- copy-thread indices (512 threads, 6 cp.async each per stage) ----
    int aRow  = tid >> 2;              // A row (0..127), 4 threads/row
    int aSeg  = (tid & 3) * 16;        // k offset 0,16,32,48 (fp16 units)
    int bRow  = tid >> 3;              // B k row (0..63), 8 threads/row
    int bCol  = (tid & 7) * 16;        // B n offset within 128-col sub-tile

    int tokA = (MODE == 0) ? sTok[aRow] : -1;
    bool aValid = (MODE == 0) ? (tokA >= 0) : ((rowBase + aRow) < count);
    int aSize = aValid ? 16 : 0;
    const __half* aP;
    if (MODE == 0) {
        aP = g_xH + (size_t)(tokA < 0 ? 0 : tokA) * DMODEL;
    } else {
        aP = g_hH + ((size_t)e * CAP + rowBase + aRow) * (size_t)DHID;
    }
    const __half* bP = ((MODE == 0) ? g_w1H : g_w2H)
        + (size_t)e * Ktot * Ntot + (size_t)bRow * Ntot + colBase + bCol;

    uint32_t aDst  = (uint32_t)aRow * (A_STRIDE * 2) + (uint32_t)aSeg * 2;  // bytes
    uint32_t bDst0 = bswz(bRow, bCol * 2);
    uint32_t bDst1 = bswz(bRow, bCol * 2 + 16);
    const int nIter = Ktot / BK;

    auto issue_stage = [&](int i) {
        uint32_t base = smBase + (uint32_t)(i % NSTAGE) * STAGE_B;
        int k0 = i * BK;
        const __half* bSrc = bP + (size_t)k0 * Ntot;
        cp_async16(base + aDst,       aP + k0 + aSeg,     aSize);
        cp_async16(base + aDst + 16u, aP + k0 + aSeg + 8, aSize);
        uint32_t bb = base + A_PLANE;
#pragma unroll
        for (int sub = 0; sub < 2; sub++) {           // two 128-col sub-tiles
            cp_async16(bb + bDst0, bSrc,     16);
            cp_async16(bb + bDst1, bSrc + 8, 16);
            bb += SUBB;
            bSrc += 128;
        }
    };

    issue_stage(0); CP_COMMIT();
    issue_stage(1); CP_COMMIT();
    issue_stage(2); CP_COMMIT();

    for (int i = 0; i < nIter; i++) {
        CP_WAIT2();            // stage i landed (<= 2 newer groups pending)
        __syncthreads();
        if (i + 3 < nIter) issue_stage(i + 3);
        CP_COMMIT();

        uint32_t base = smBase + (uint32_t)(i % NSTAGE) * STAGE_B;
        uint32_t pA = base;
        uint32_t pB = base + A_PLANE;

#pragma unroll
        for (int s = 0; s < 4; s++) {
            int kk = s * 16;
            // ---- A fragments via ldmatrix.x4 (non-trans) ----
            uint32_t aF[2][4];
#pragma unroll
            for (int mi = 0; mi < 2; mi++) {
                uint32_t ao = pA + (uint32_t)(((warpM * 32 + mi * 16 + aLmRow) * A_STRIDE
                                               + kk + aLmCol) * 2);
                ldsm_x4(aF[mi][0], aF[mi][1], aF[mi][2], aF[mi][3], ao);
            }
            // ---- B fragments: warp covers 64 cols = 4 x n16 panels ----
            uint32_t bh[4][4];
#pragma unroll
            for (int u = 0; u < 4; u++) {
                int n0 = warpN * 64 + u * 16;
                uint32_t off = (uint32_t)((n0 >> 7) * SUBB)
                             + bswz(kk + lm_kd, ((n0 & 127) + lm_nd) * 2);
                ldsm_x4_t(bh[u][0], bh[u][1], bh[u][2], bh[u][3], pB + off);
            }
            // ---- MMAs (16 distinct accumulators; no consecutive RAW) ----
#pragma unroll
            for (int ni = 0; ni < 8; ni++) {
                uint32_t bp[2] = { bh[ni >> 1][(ni & 1) * 2], bh[ni >> 1][(ni & 1) * 2 + 1] };
#pragma unroll
                for (int mi = 0; mi < 2; mi++) mma_f16(acc[mi][ni], aF[mi], bp);
            }
        }
        __syncthreads();       // all reads of stage i done before it is rewritten
    }

    // ---- epilogue ----
#pragma unroll
    for (int mi = 0; mi < 2; mi++) {
#pragma unroll
        for (int rsel = 0; rsel < 2; rsel++) {
            int rloc = warpM * 32 + mi * 16 + gid + rsel * 8;
            int tok = sTok[rloc];
            if (tok < 0) continue;
#pragma unroll
            for (int ni = 0; ni < 8; ni++) {
                int cloc = warpN * 64 + ni * 8 + tig * 2;
                float2 bv = *(const float2*)(bias + cloc);
                float v0 = acc[mi][ni][rsel * 2 + 0] + bv.x;
                float v1 = acc[mi][ni][rsel * 2 + 1] + bv.y;
                if (MODE == 0) {
                    v0 = v0 > 0.f ? v0 : 0.f;
                    v1 = v1 > 0.f ? v1 : 0.f;
                    __half2 H = {__float2half_rn(v0), __float2half_rn(v1)};
                    size_t o = ((size_t)e * CAP + rowBase + rloc) * DHID + colBase + cloc;
                    *(uint32_t*)(g_hH + o) = *(uint32_t*)&H;
                } else {
                    float* op = outg + (size_t)tok * DMODEL + colBase + cloc;
                    *(float2*)op = make_float2(v0, v1);
                }
            }
        }
    }
}

// ---------------- launch ----------------------------------------------------
extern "C" void kernel_launch(void* const* d_in, const int* in_sizes, int n_in,
                              void* d_out, int out_size) {
    const float* x  = (const float*)d_in[0];
    const float* Wg = (const float*)d_in[1];
    const float* bg = (const float*)d_in[2];
    const float* W1 = (const float*)d_in[3];
    const float* b1 = (const float*)d_in[4];
    const float* W2 = (const float*)d_in[5];
    const float* b2 = (const float*)d_in[6];
    float* out = (float*)d_out;

    cudaFuncSetAttribute(moe_ffn<0>, cudaFuncAttributeMaxDynamicSharedMemorySize, FFN_SMEM);
    cudaFuncSetAttribute(moe_ffn<1>, cudaFuncAttributeMaxDynamicSharedMemorySize, FFN_SMEM);

    cudaMemsetAsync(d_out, 0, (size_t)out_size * sizeof(float));

    moe_router<<<NTOK / 8, 256>>>(x, Wg, bg);
    moe_scan<<<1, 256>>>();
    convert_all<<<CVT_BLOCKS, 256>>>(x, W1, W2);

    moe_ffn<0><<<dim3(DHID / BN, CAP / BM, NEXP), 512, FFN_SMEM>>>(b1, nullptr);
    moe_ffn<1><<<dim3(DMODEL / BN, CAP / BM, NEXP), 512, FFN_SMEM>>>(b2, out);
}